// round 13
// baseline (speedup 1.0000x reference)
#include <cuda_runtime.h>

// ---------------------------------------------------------------------------
// DMoN: GCNConv(128->16) + ReLU + Linear(16->16) + softmax
// N=100000 nodes, E=3.2M edges.
// R13: R11 base + split-wavefront edge passes: each multi-line LDG/RED is
//      split into lane-group-predicated instructions (predicate INSIDE asm)
//      so L1tex wavefronts come from multiple instructions (~1.0 cyc/wf
//      cross-instruction) instead of one instruction's replay chain (2.07).
// ---------------------------------------------------------------------------

#define FIN 128
#define HID 16
#define CLS 16
#define MAXN 100000

__device__ __align__(16) float g_deg[MAXN];        // degree, then dinv (in place)
__device__ __align__(16) float g_h[MAXN * HID];    // x @ W1, then pre-scaled by dinv
__device__ __align__(16) float g_agg[MAXN * HID];  // zeroed in transform branch
__device__ int g_is64;                             // 1 if edge_index stored as int64

__device__ __forceinline__ void gdc_launch_dependents() {
    asm volatile("griddepcontrol.launch_dependents;");
}
__device__ __forceinline__ void gdc_wait() {
    asm volatile("griddepcontrol.wait;" ::: "memory");
}

__device__ __forceinline__ int edge_at(const void* edges, long long i, int is64) {
    if (is64) return (int)((const long long*)edges)[i];
    return ((const int*)edges)[i];
}

// ---- lane-group predicated memory ops (predicate inside asm: not foldable) --
__device__ __forceinline__ void pred_ld_v4(int gv, int k, const float* a, float4& v) {
    asm volatile("{\n\t"
                 ".reg .pred p;\n\t"
                 "setp.eq.s32 p, %4, %5;\n\t"
                 "@p ld.global.v4.f32 {%0, %1, %2, %3}, [%6];\n\t"
                 "}"
                 : "+f"(v.x), "+f"(v.y), "+f"(v.z), "+f"(v.w)
                 : "r"(gv), "r"(k), "l"(a)
                 : "memory");
}
__device__ __forceinline__ void pred_red_v4(int gv, int k, float* a, float4 v) {
    asm volatile("{\n\t"
                 ".reg .pred p;\n\t"
                 "setp.eq.s32 p, %0, %1;\n\t"
                 "@p red.global.add.v4.f32 [%2], {%3, %4, %5, %6};\n\t"
                 "}"
                 :: "r"(gv), "r"(k), "l"(a), "f"(v.x), "f"(v.y), "f"(v.z), "f"(v.w)
                 : "memory");
}
__device__ __forceinline__ void pred_red_one(int gv, int k, float* a) {
    asm volatile("{\n\t"
                 ".reg .pred p;\n\t"
                 "setp.eq.s32 p, %0, %1;\n\t"
                 "@p red.global.add.f32 [%2], %3;\n\t"
                 "}"
                 :: "r"(gv), "r"(k), "l"(a), "f"(1.0f)
                 : "memory");
}

// ---------------------------------------------------------------------------
// init + dtype detect (block 0): deg = 1 (self loop).
// ---------------------------------------------------------------------------
__global__ void __launch_bounds__(256) init_detect_kernel(
    int n, const int* __restrict__ e32, int nwords32) {
    gdc_launch_dependents();
    if (blockIdx.x == 0) {
        __shared__ int nonzero;
        if (threadIdx.x == 0) nonzero = 0;
        __syncthreads();
        long long stride = nwords32 / (long long)blockDim.x;
        if (stride < 2) stride = 2;
        long long idx = ((long long)threadIdx.x * stride) | 1;
        if (idx < (long long)nwords32 && e32[idx] != 0) nonzero = 1;
        __syncthreads();
        if (threadIdx.x == 0) g_is64 = (nonzero == 0) ? 1 : 0;
    }
    int i = blockIdx.x * blockDim.x + threadIdx.x;
    if (i >= n) return;
    g_deg[i] = 1.0f;
}

// ---------------------------------------------------------------------------
// packed f32x2 FMA helpers
// ---------------------------------------------------------------------------
__device__ __forceinline__ unsigned long long pack2(float v) {
    unsigned long long r;
    asm("mov.b64 %0, {%1, %1};" : "=l"(r) : "r"(__float_as_uint(v)));
    return r;
}
__device__ __forceinline__ void fma2(unsigned long long& acc,
                                     unsigned long long a, unsigned long long b) {
    asm("fma.rn.f32x2 %0, %1, %2, %0;" : "+l"(acc) : "l"(a), "l"(b));
}

// ---------------------------------------------------------------------------
// fused: blocks [0,nbT) h = x @ W1 (+ zero agg rows); blocks [nbT,..) degree.
// deg: 1 edge/thread (coalesced idx load), 8 x 4-lane predicated REDs.
// ---------------------------------------------------------------------------
__global__ void __launch_bounds__(256) transform_deg_kernel(
    const float* __restrict__ x, const float* __restrict__ W1,
    const void* __restrict__ edges, int n, int E, int nbT) {
    gdc_launch_dependents();
    if (blockIdx.x < nbT) {
        // ---- transform branch: inputs only, no wait ----
        __shared__ float Ws[FIN * HID];  // 8 KB
        for (int i = threadIdx.x; i < FIN * HID; i += blockDim.x) Ws[i] = W1[i];
        __syncthreads();

        int node = blockIdx.x * blockDim.x + threadIdx.x;
        if (node >= n) return;

        {
            float4 z = make_float4(0.f, 0.f, 0.f, 0.f);
            float4* a = (float4*)(g_agg + (size_t)node * HID);
            a[0] = z; a[1] = z; a[2] = z; a[3] = z;
        }

        const float4* xr = (const float4*)(x + (size_t)node * FIN);
        unsigned long long acc[8];
#pragma unroll
        for (int j = 0; j < 8; j++) acc[j] = 0ULL;

#pragma unroll 8
        for (int k4 = 0; k4 < FIN / 4; k4++) {
            float4 xv = xr[k4];
#pragma unroll
            for (int sub = 0; sub < 4; sub++) {
                float xs = (sub == 0) ? xv.x : (sub == 1) ? xv.y : (sub == 2) ? xv.z : xv.w;
                unsigned long long xp = pack2(xs);
                const unsigned long long* wr =
                    (const unsigned long long*)(Ws + (k4 * 4 + sub) * HID);
#pragma unroll
                for (int j = 0; j < 8; j++) fma2(acc[j], xp, wr[j]);
            }
        }

        float hrow[16];
#pragma unroll
        for (int j = 0; j < 8; j++) {
            unsigned int lo, hi;
            asm("mov.b64 {%0, %1}, %2;" : "=r"(lo), "=r"(hi) : "l"(acc[j]));
            hrow[2 * j]     = __uint_as_float(lo);
            hrow[2 * j + 1] = __uint_as_float(hi);
        }
        float4* hout = (float4*)(g_h + (size_t)node * HID);
#pragma unroll
        for (int q = 0; q < 4; q++)
            hout[q] = make_float4(hrow[4 * q], hrow[4 * q + 1],
                                  hrow[4 * q + 2], hrow[4 * q + 3]);
    } else {
        // ---- degree branch: depends on init (g_is64, g_deg=1) ----
        gdc_wait();
        int is64 = g_is64;
        int lane = threadIdx.x & 31;
        long long eidx = (long long)(blockIdx.x - nbT) * blockDim.x + threadIdx.x;
        int gv = -1;
        int d = 0;
        if (eidx < E) {
            d = edge_at(edges, (long long)E + eidx, is64);
            gv = lane >> 2;  // 8 groups of 4 lanes -> <=4 lines per RED
        }
        float* ad = &g_deg[d];
#pragma unroll
        for (int k = 0; k < 8; k++) pred_red_one(gv, k, ad);
    }
}

// ---------------------------------------------------------------------------
// dinv = rsqrt(deg); h[i] *= dinv. Triggers dependents AFTER wait.
// ---------------------------------------------------------------------------
__global__ void __launch_bounds__(256) rsqrt_scale_kernel(int n) {
    gdc_wait();
    gdc_launch_dependents();
    int i = blockIdx.x * blockDim.x + threadIdx.x;
    if (i >= n) return;
    float dinv = rsqrtf(g_deg[i]);
    g_deg[i] = dinv;
    float4* h = (float4*)(g_h + (size_t)i * HID);
#pragma unroll
    for (int q = 0; q < 4; q++) {
        float4 v = h[q];
        v.x *= dinv; v.y *= dinv; v.z *= dinv; v.w *= dinv;
        h[q] = v;
    }
}

// ---------------------------------------------------------------------------
// edge scatter: agg[dst] += h_s[src]
// 4 threads/edge-quarter; 2 far-apart iterations per thread (R11 layout).
// Gather/RED split into 4 x 8-lane (2-edge) predicated instructions.
// ---------------------------------------------------------------------------
__global__ void __launch_bounds__(256) scatter_kernel(const void* __restrict__ edges,
                                                      int E, long long half) {
    gdc_launch_dependents();  // finalize pre-wait touches inputs only: safe
    int is64 = g_is64;
    long long totalq = 4LL * E;
    long long t = (long long)blockIdx.x * blockDim.x + threadIdx.x;
    int lane = threadIdx.x & 31;
    int grp = lane >> 3;  // 4 groups of 8 lanes = 2 edges per instruction

    // iter-0 prefetch (pre-wait): inputs + upstream completed via rsqrt's wait
    bool h0 = (t < totalq);
    long long e0 = t >> 2;
    int q0 = (int)(t & 3);
    int s0 = 0, d0 = 0;
    if (h0) {
        s0 = edge_at(edges, e0, is64);
        d0 = edge_at(edges, (long long)E + e0, is64);
    }
    gdc_wait();
    {
        int gv = h0 ? grp : -1;
        const float* ha = g_h + (size_t)(unsigned)s0 * HID + 4 * q0;
        float* ad = g_agg + (size_t)(unsigned)d0 * HID + 4 * q0;
        float4 v = make_float4(0.f, 0.f, 0.f, 0.f);
#pragma unroll
        for (int k = 0; k < 4; k++) pred_ld_v4(gv, k, ha, v);
#pragma unroll
        for (int k = 0; k < 4; k++) pred_red_v4(gv, k, ad, v);
    }
    t += half;
    {
        bool h1 = (t < totalq);
        long long e = t >> 2;
        int q = (int)(t & 3);
        int s = 0, d = 0;
        if (h1) {
            s = edge_at(edges, e, is64);
            d = edge_at(edges, (long long)E + e, is64);
        }
        int gv = h1 ? grp : -1;
        const float* ha = g_h + (size_t)(unsigned)s * HID + 4 * q;
        float* ad = g_agg + (size_t)(unsigned)d * HID + 4 * q;
        float4 v = make_float4(0.f, 0.f, 0.f, 0.f);
#pragma unroll
        for (int k = 0; k < 4; k++) pred_ld_v4(gv, k, ha, v);
#pragma unroll
        for (int k = 0; k < 4; k++) pred_red_v4(gv, k, ad, v);
    }
}

// ---------------------------------------------------------------------------
// epilogue: a = relu(dinv*(agg + h_s) + b1), logits = a@Wp+bp, softmax
// ---------------------------------------------------------------------------
__global__ void __launch_bounds__(256) finalize_kernel(
    const float* __restrict__ b1, const float* __restrict__ Wp,
    const float* __restrict__ bp, float* __restrict__ out, int n) {
    __shared__ float Wps[HID * CLS];
    __shared__ float bps[CLS];
    __shared__ float b1s[HID];
    for (int i = threadIdx.x; i < HID * CLS; i += blockDim.x) Wps[i] = Wp[i];
    if (threadIdx.x < CLS) bps[threadIdx.x] = bp[threadIdx.x];
    if (threadIdx.x < HID) b1s[threadIdx.x] = b1[threadIdx.x];
    gdc_wait();
    __syncthreads();

    int i = blockIdx.x * blockDim.x + threadIdx.x;
    if (i >= n) return;

    float dinv = g_deg[i];

    float a[HID];
    const float4* ag = (const float4*)(g_agg + (size_t)i * HID);
    const float4* hv = (const float4*)(g_h + (size_t)i * HID);
#pragma unroll
    for (int q = 0; q < 4; q++) {
        float4 av = ag[q];
        float4 hh = hv[q];
        a[4 * q + 0] = fmaxf(fmaf(av.x + hh.x, dinv, b1s[4 * q + 0]), 0.0f);
        a[4 * q + 1] = fmaxf(fmaf(av.y + hh.y, dinv, b1s[4 * q + 1]), 0.0f);
        a[4 * q + 2] = fmaxf(fmaf(av.z + hh.z, dinv, b1s[4 * q + 2]), 0.0f);
        a[4 * q + 3] = fmaxf(fmaf(av.w + hh.w, dinv, b1s[4 * q + 3]), 0.0f);
    }

    float lg[CLS];
#pragma unroll
    for (int c = 0; c < CLS; c++) lg[c] = bps[c];
#pragma unroll
    for (int j = 0; j < HID; j++) {
        float aj = a[j];
#pragma unroll
        for (int c = 0; c < CLS; c++) lg[c] = fmaf(aj, Wps[j * CLS + c], lg[c]);
    }

    float m = lg[0];
#pragma unroll
    for (int c = 1; c < CLS; c++) m = fmaxf(m, lg[c]);
    float ssum = 0.0f;
#pragma unroll
    for (int c = 0; c < CLS; c++) { lg[c] = __expf(lg[c] - m); ssum += lg[c]; }
    float inv = 1.0f / ssum;
#pragma unroll
    for (int c = 0; c < CLS; c++) lg[c] *= inv;

    float4* o = (float4*)(out + (size_t)i * CLS);
#pragma unroll
    for (int q = 0; q < 4; q++)
        o[q] = make_float4(lg[4 * q], lg[4 * q + 1], lg[4 * q + 2], lg[4 * q + 3]);
}

// ---------------------------------------------------------------------------
// launch (5 kernels, PDL edges between consecutive ones)
// ---------------------------------------------------------------------------
template <typename... ExpT, typename... ActT>
static void launch_k(void (*k)(ExpT...), int grid, bool pdl, ActT... args) {
    cudaLaunchConfig_t cfg = {};
    cfg.gridDim = dim3((unsigned)grid, 1, 1);
    cfg.blockDim = dim3(256, 1, 1);
    cfg.dynamicSmemBytes = 0;
    cfg.stream = 0;
    cudaLaunchAttribute attr[1];
    if (pdl) {
        attr[0].id = cudaLaunchAttributeProgrammaticStreamSerialization;
        attr[0].val.programmaticStreamSerializationAllowed = 1;
        cfg.attrs = attr;
        cfg.numAttrs = 1;
    }
    cudaLaunchKernelEx(&cfg, k, args...);
}

extern "C" void kernel_launch(void* const* d_in, const int* in_sizes, int n_in,
                              void* d_out, int out_size) {
    const float* x  = (const float*)d_in[0];
    const float* W1 = (const float*)d_in[1];
    const float* b1 = (const float*)d_in[2];
    const float* Wp = (const float*)d_in[3];
    const float* bp = (const float*)d_in[4];
    const void*  edges = d_in[5];

    int n = in_sizes[0] / FIN;       // 100000
    int E = in_sizes[5] / 2;         // 3200000

    int nb  = (n + 255) / 256;
    int nbT = nb;
    int degBlocks = (E + 255) / 256;  // 1 edge per thread

    long long totalq = 4LL * E;
    long long half = (totalq + 1) / 2;
    int sb = (int)((half + 255) / 256);

    launch_k(init_detect_kernel, nb, false, n, (const int*)edges, in_sizes[5]);
    launch_k(transform_deg_kernel, nbT + degBlocks, true, x, W1, edges, n, E, nbT);
    launch_k(rsqrt_scale_kernel, nb, true, n);
    launch_k(scatter_kernel, sb, true, edges, E, half);
    launch_k(finalize_kernel, nb, true, b1, Wp, bp, (float*)d_out, n);
}

// round 14
// speedup vs baseline: 1.0915x; 1.0915x over previous
#include <cuda_runtime.h>

// ---------------------------------------------------------------------------
// DMoN: GCNConv(128->16) + ReLU + Linear(16->16) + softmax
// N=100000 nodes, E=3.2M edges.
// R14 (final): R11 configuration — the measured optimum.
//   - transform || deg fused kernel (transform-first block order, DEG_EPT=4)
//   - scatter: 4-lane LDG.128/RED.v4 per edge-quarter, 2 far-apart iters
//     (empirical L1tex divergent-wavefront floor: ~2 wf/edge @ 2.07 cyc)
//   - PDL between consecutive kernels (prologue overlap)
//   - explicit init + global dtype flag (zero-state/inline-detect variants
//     faulted in R4/R5/R8 and are banned)
//   Only change vs R11: rsqrt_scale handles 2 nodes/thread.
// ---------------------------------------------------------------------------

#define FIN 128
#define HID 16
#define CLS 16
#define MAXN 100000

__device__ __align__(16) float g_deg[MAXN];        // degree, then dinv (in place)
__device__ __align__(16) float g_h[MAXN * HID];    // x @ W1, then pre-scaled by dinv
__device__ __align__(16) float g_agg[MAXN * HID];  // zeroed in transform branch
__device__ int g_is64;                             // 1 if edge_index stored as int64

__device__ __forceinline__ void gdc_launch_dependents() {
    asm volatile("griddepcontrol.launch_dependents;");
}
__device__ __forceinline__ void gdc_wait() {
    asm volatile("griddepcontrol.wait;" ::: "memory");
}

__device__ __forceinline__ int edge_at(const void* edges, long long i, int is64) {
    if (is64) return (int)((const long long*)edges)[i];
    return ((const int*)edges)[i];
}

// ---------------------------------------------------------------------------
// init + dtype detect (block 0): deg = 1 (self loop).
// int64 nonneg < 2^31 -> every odd 32-bit word is 0; 256 samples.
// ---------------------------------------------------------------------------
__global__ void __launch_bounds__(256) init_detect_kernel(
    int n, const int* __restrict__ e32, int nwords32) {
    gdc_launch_dependents();  // transform branch reads only inputs: safe early
    if (blockIdx.x == 0) {
        __shared__ int nonzero;
        if (threadIdx.x == 0) nonzero = 0;
        __syncthreads();
        long long stride = nwords32 / (long long)blockDim.x;
        if (stride < 2) stride = 2;
        long long idx = ((long long)threadIdx.x * stride) | 1;
        if (idx < (long long)nwords32 && e32[idx] != 0) nonzero = 1;
        __syncthreads();
        if (threadIdx.x == 0) g_is64 = (nonzero == 0) ? 1 : 0;
    }
    int i = blockIdx.x * blockDim.x + threadIdx.x;
    if (i >= n) return;
    g_deg[i] = 1.0f;
}

// ---------------------------------------------------------------------------
// packed f32x2 FMA helpers
// ---------------------------------------------------------------------------
__device__ __forceinline__ unsigned long long pack2(float v) {
    unsigned long long r;
    asm("mov.b64 %0, {%1, %1};" : "=l"(r) : "r"(__float_as_uint(v)));
    return r;
}
__device__ __forceinline__ void fma2(unsigned long long& acc,
                                     unsigned long long a, unsigned long long b) {
    asm("fma.rn.f32x2 %0, %1, %2, %0;" : "+l"(acc) : "l"(a), "l"(b));
}

// ---------------------------------------------------------------------------
// fused: blocks [0,nbT) h = x @ W1 (+ zero agg rows, inputs only -> no wait);
// blocks [nbT,..) degree scatter (waits on init for g_is64 / g_deg=1).
// ---------------------------------------------------------------------------
#define DEG_EPT 4

__global__ void __launch_bounds__(256) transform_deg_kernel(
    const float* __restrict__ x, const float* __restrict__ W1,
    const void* __restrict__ edges, int n, int E, int nbT) {
    gdc_launch_dependents();
    if (blockIdx.x < nbT) {
        // ---- transform branch: independent of init_detect, no wait ----
        __shared__ float Ws[FIN * HID];  // 8 KB
        for (int i = threadIdx.x; i < FIN * HID; i += blockDim.x) Ws[i] = W1[i];
        __syncthreads();

        int node = blockIdx.x * blockDim.x + threadIdx.x;
        if (node >= n) return;

        {
            float4 z = make_float4(0.f, 0.f, 0.f, 0.f);
            float4* a = (float4*)(g_agg + (size_t)node * HID);
            a[0] = z; a[1] = z; a[2] = z; a[3] = z;
        }

        const float4* xr = (const float4*)(x + (size_t)node * FIN);
        unsigned long long acc[8];
#pragma unroll
        for (int j = 0; j < 8; j++) acc[j] = 0ULL;

#pragma unroll 8
        for (int k4 = 0; k4 < FIN / 4; k4++) {
            float4 xv = xr[k4];
#pragma unroll
            for (int sub = 0; sub < 4; sub++) {
                float xs = (sub == 0) ? xv.x : (sub == 1) ? xv.y : (sub == 2) ? xv.z : xv.w;
                unsigned long long xp = pack2(xs);
                const unsigned long long* wr =
                    (const unsigned long long*)(Ws + (k4 * 4 + sub) * HID);
#pragma unroll
                for (int j = 0; j < 8; j++) fma2(acc[j], xp, wr[j]);
            }
        }

        float hrow[16];
#pragma unroll
        for (int j = 0; j < 8; j++) {
            unsigned int lo, hi;
            asm("mov.b64 {%0, %1}, %2;" : "=r"(lo), "=r"(hi) : "l"(acc[j]));
            hrow[2 * j]     = __uint_as_float(lo);
            hrow[2 * j + 1] = __uint_as_float(hi);
        }
        float4* hout = (float4*)(g_h + (size_t)node * HID);
#pragma unroll
        for (int q = 0; q < 4; q++)
            hout[q] = make_float4(hrow[4 * q], hrow[4 * q + 1],
                                  hrow[4 * q + 2], hrow[4 * q + 3]);
    } else {
        // ---- degree branch: depends on init (g_is64, g_deg=1) ----
        gdc_wait();
        int is64 = g_is64;
        long long t = (long long)(blockIdx.x - nbT) * blockDim.x + threadIdx.x;
        long long base = t * DEG_EPT;
        if (base >= E) return;
        if (base + DEG_EPT <= E) {
            int dd[DEG_EPT];
            if (is64) {
                const longlong2* p =
                    (const longlong2*)((const long long*)edges + E + base);
                longlong2 a = p[0], b = p[1];
                dd[0] = (int)a.x; dd[1] = (int)a.y; dd[2] = (int)b.x; dd[3] = (int)b.y;
            } else {
                int4 a = *(const int4*)((const int*)edges + E + base);
                dd[0] = a.x; dd[1] = a.y; dd[2] = a.z; dd[3] = a.w;
            }
#pragma unroll
            for (int k = 0; k < DEG_EPT; k++)
                asm volatile("red.global.add.f32 [%0], %1;"
                             :: "l"(&g_deg[dd[k]]), "f"(1.0f) : "memory");
        } else {
            for (long long e = base; e < E; e++) {
                int d = edge_at(edges, (long long)E + e, is64);
                asm volatile("red.global.add.f32 [%0], %1;"
                             :: "l"(&g_deg[d]), "f"(1.0f) : "memory");
            }
        }
    }
}

// ---------------------------------------------------------------------------
// dinv = rsqrt(deg); h[i] *= dinv. 2 nodes per thread. Triggers dependents
// AFTER wait so scatter's pre-wait prologue sees completed init+transform.
// ---------------------------------------------------------------------------
__global__ void __launch_bounds__(256) rsqrt_scale_kernel(int n) {
    gdc_wait();
    gdc_launch_dependents();
    int base = (blockIdx.x * blockDim.x + threadIdx.x) * 2;
#pragma unroll
    for (int u = 0; u < 2; u++) {
        int i = base + u;
        if (i >= n) break;
        float dinv = rsqrtf(g_deg[i]);
        g_deg[i] = dinv;
        float4* h = (float4*)(g_h + (size_t)i * HID);
#pragma unroll
        for (int q = 0; q < 4; q++) {
            float4 v = h[q];
            v.x *= dinv; v.y *= dinv; v.z *= dinv; v.w *= dinv;
            h[q] = v;
        }
    }
}

// ---------------------------------------------------------------------------
// edge scatter: agg[dst] += h_s[src]  [R11/R6 body — measured floor]
// 4 threads/edge-quarter; each thread handles quarters t and t + half.
// iter-0 indices prefetched pre-wait (inputs + completed upstream only).
// ---------------------------------------------------------------------------
__global__ void __launch_bounds__(256) scatter_kernel(const void* __restrict__ edges,
                                                      int E, long long half) {
    gdc_launch_dependents();  // finalize pre-wait touches inputs only: safe
    int is64 = g_is64;
    long long totalq = 4LL * E;
    long long t = (long long)blockIdx.x * blockDim.x + threadIdx.x;
    int s0 = 0, d0 = 0;
    bool h0 = (t < totalq);
    long long e0 = t >> 2;
    int q0 = (int)(t & 3);
    if (h0) {
        s0 = edge_at(edges, e0, is64);
        d0 = edge_at(edges, (long long)E + e0, is64);
    }
    gdc_wait();
    if (h0) {
        float4 v = ((const float4*)(g_h + (size_t)s0 * HID))[q0];
        float* ad = g_agg + (size_t)d0 * HID + 4 * q0;
        asm volatile("red.global.add.v4.f32 [%0], {%1, %2, %3, %4};"
                     :: "l"(ad), "f"(v.x), "f"(v.y), "f"(v.z), "f"(v.w)
                     : "memory");
    }
    t += half;
    if (t < totalq) {
        long long e = t >> 2;
        int q = (int)(t & 3);
        int s = edge_at(edges, e, is64);
        int d = edge_at(edges, (long long)E + e, is64);
        float4 v = ((const float4*)(g_h + (size_t)s * HID))[q];
        float* ad = g_agg + (size_t)d * HID + 4 * q;
        asm volatile("red.global.add.v4.f32 [%0], {%1, %2, %3, %4};"
                     :: "l"(ad), "f"(v.x), "f"(v.y), "f"(v.z), "f"(v.w)
                     : "memory");
    }
}

// ---------------------------------------------------------------------------
// epilogue: a = relu(dinv*(agg + h_s) + b1), logits = a@Wp+bp, softmax
// (smem weight loads pre-wait)
// ---------------------------------------------------------------------------
__global__ void __launch_bounds__(256) finalize_kernel(
    const float* __restrict__ b1, const float* __restrict__ Wp,
    const float* __restrict__ bp, float* __restrict__ out, int n) {
    __shared__ float Wps[HID * CLS];
    __shared__ float bps[CLS];
    __shared__ float b1s[HID];
    for (int i = threadIdx.x; i < HID * CLS; i += blockDim.x) Wps[i] = Wp[i];
    if (threadIdx.x < CLS) bps[threadIdx.x] = bp[threadIdx.x];
    if (threadIdx.x < HID) b1s[threadIdx.x] = b1[threadIdx.x];
    gdc_wait();
    __syncthreads();

    int i = blockIdx.x * blockDim.x + threadIdx.x;
    if (i >= n) return;

    float dinv = g_deg[i];

    float a[HID];
    const float4* ag = (const float4*)(g_agg + (size_t)i * HID);
    const float4* hv = (const float4*)(g_h + (size_t)i * HID);
#pragma unroll
    for (int q = 0; q < 4; q++) {
        float4 av = ag[q];
        float4 hh = hv[q];
        a[4 * q + 0] = fmaxf(fmaf(av.x + hh.x, dinv, b1s[4 * q + 0]), 0.0f);
        a[4 * q + 1] = fmaxf(fmaf(av.y + hh.y, dinv, b1s[4 * q + 1]), 0.0f);
        a[4 * q + 2] = fmaxf(fmaf(av.z + hh.z, dinv, b1s[4 * q + 2]), 0.0f);
        a[4 * q + 3] = fmaxf(fmaf(av.w + hh.w, dinv, b1s[4 * q + 3]), 0.0f);
    }

    float lg[CLS];
#pragma unroll
    for (int c = 0; c < CLS; c++) lg[c] = bps[c];
#pragma unroll
    for (int j = 0; j < HID; j++) {
        float aj = a[j];
#pragma unroll
        for (int c = 0; c < CLS; c++) lg[c] = fmaf(aj, Wps[j * CLS + c], lg[c]);
    }

    float m = lg[0];
#pragma unroll
    for (int c = 1; c < CLS; c++) m = fmaxf(m, lg[c]);
    float ssum = 0.0f;
#pragma unroll
    for (int c = 0; c < CLS; c++) { lg[c] = __expf(lg[c] - m); ssum += lg[c]; }
    float inv = 1.0f / ssum;
#pragma unroll
    for (int c = 0; c < CLS; c++) lg[c] *= inv;

    float4* o = (float4*)(out + (size_t)i * CLS);
#pragma unroll
    for (int q = 0; q < 4; q++)
        o[q] = make_float4(lg[4 * q], lg[4 * q + 1], lg[4 * q + 2], lg[4 * q + 3]);
}

// ---------------------------------------------------------------------------
// launch (5 kernels, PDL edges between consecutive ones)
// ---------------------------------------------------------------------------
template <typename... ExpT, typename... ActT>
static void launch_k(void (*k)(ExpT...), int grid, bool pdl, ActT... args) {
    cudaLaunchConfig_t cfg = {};
    cfg.gridDim = dim3((unsigned)grid, 1, 1);
    cfg.blockDim = dim3(256, 1, 1);
    cfg.dynamicSmemBytes = 0;
    cfg.stream = 0;  // legacy default stream (same as <<<>>>)
    cudaLaunchAttribute attr[1];
    if (pdl) {
        attr[0].id = cudaLaunchAttributeProgrammaticStreamSerialization;
        attr[0].val.programmaticStreamSerializationAllowed = 1;
        cfg.attrs = attr;
        cfg.numAttrs = 1;
    }
    cudaLaunchKernelEx(&cfg, k, args...);
}

extern "C" void kernel_launch(void* const* d_in, const int* in_sizes, int n_in,
                              void* d_out, int out_size) {
    const float* x  = (const float*)d_in[0];
    const float* W1 = (const float*)d_in[1];
    const float* b1 = (const float*)d_in[2];
    const float* Wp = (const float*)d_in[3];
    const float* bp = (const float*)d_in[4];
    const void*  edges = d_in[5];

    int n = in_sizes[0] / FIN;       // 100000
    int E = in_sizes[5] / 2;         // 3200000

    int nb  = (n + 255) / 256;
    int nbT = nb;
    int nb2 = (n + 511) / 512;       // rsqrt_scale: 2 nodes/thread
    int degBlocks = (E + 256 * DEG_EPT - 1) / (256 * DEG_EPT);

    long long totalq = 4LL * E;
    long long half = (totalq + 1) / 2;
    int sb = (int)((half + 255) / 256);

    launch_k(init_detect_kernel, nb, false, n, (const int*)edges, in_sizes[5]);
    launch_k(transform_deg_kernel, nbT + degBlocks, true, x, W1, edges, n, E, nbT);
    launch_k(rsqrt_scale_kernel, nb2, true, n);
    launch_k(scatter_kernel, sb, true, edges, E, half);
    launch_k(finalize_kernel, nb, true, b1, Wp, bp, (float*)d_out, n);
}

// round 15
// speedup vs baseline: 1.1353x; 1.0401x over previous
#include <cuda_runtime.h>

// ---------------------------------------------------------------------------
// DMoN: GCNConv(128->16) + ReLU + Linear(16->16) + softmax
// N=100000 nodes, E=3.2M edges.
// R15 (final): exact R11 configuration — the measured optimum (102.9us).
//   - transform || deg fused kernel (transform-first, DEG_EPT=4)
//   - scatter: 4-lane LDG.128/RED.v4 per edge-quarter, 2 far-apart iters
//     (L1tex divergent-wavefront floor: ~2 wf/edge @ 2.07 cyc — confirmed
//      by R6/R11/R12/R14; 16-lane and predicated-split alternatives regressed)
//   - PDL between consecutive kernels (verified -1.6us)
//   - explicit init + global dtype flag (zero-state/inline-detect faulted)
// ---------------------------------------------------------------------------

#define FIN 128
#define HID 16
#define CLS 16
#define MAXN 100000

__device__ __align__(16) float g_deg[MAXN];        // degree, then dinv (in place)
__device__ __align__(16) float g_h[MAXN * HID];    // x @ W1, then pre-scaled by dinv
__device__ __align__(16) float g_agg[MAXN * HID];  // zeroed in transform branch
__device__ int g_is64;                             // 1 if edge_index stored as int64

__device__ __forceinline__ void gdc_launch_dependents() {
    asm volatile("griddepcontrol.launch_dependents;");
}
__device__ __forceinline__ void gdc_wait() {
    asm volatile("griddepcontrol.wait;" ::: "memory");
}

__device__ __forceinline__ int edge_at(const void* edges, long long i, int is64) {
    if (is64) return (int)((const long long*)edges)[i];
    return ((const int*)edges)[i];
}

// ---------------------------------------------------------------------------
// init + dtype detect (block 0): deg = 1 (self loop).
// int64 nonneg < 2^31 -> every odd 32-bit word is 0; 256 samples.
// ---------------------------------------------------------------------------
__global__ void __launch_bounds__(256) init_detect_kernel(
    int n, const int* __restrict__ e32, int nwords32) {
    gdc_launch_dependents();  // transform branch reads only inputs: safe early
    if (blockIdx.x == 0) {
        __shared__ int nonzero;
        if (threadIdx.x == 0) nonzero = 0;
        __syncthreads();
        long long stride = nwords32 / (long long)blockDim.x;
        if (stride < 2) stride = 2;
        long long idx = ((long long)threadIdx.x * stride) | 1;
        if (idx < (long long)nwords32 && e32[idx] != 0) nonzero = 1;
        __syncthreads();
        if (threadIdx.x == 0) g_is64 = (nonzero == 0) ? 1 : 0;
    }
    int i = blockIdx.x * blockDim.x + threadIdx.x;
    if (i >= n) return;
    g_deg[i] = 1.0f;
}

// ---------------------------------------------------------------------------
// packed f32x2 FMA helpers
// ---------------------------------------------------------------------------
__device__ __forceinline__ unsigned long long pack2(float v) {
    unsigned long long r;
    asm("mov.b64 %0, {%1, %1};" : "=l"(r) : "r"(__float_as_uint(v)));
    return r;
}
__device__ __forceinline__ void fma2(unsigned long long& acc,
                                     unsigned long long a, unsigned long long b) {
    asm("fma.rn.f32x2 %0, %1, %2, %0;" : "+l"(acc) : "l"(a), "l"(b));
}

// ---------------------------------------------------------------------------
// fused: blocks [0,nbT) h = x @ W1 (+ zero agg rows, inputs only -> no wait);
// blocks [nbT,..) degree scatter (waits on init for g_is64 / g_deg=1).
// ---------------------------------------------------------------------------
#define DEG_EPT 4

__global__ void __launch_bounds__(256) transform_deg_kernel(
    const float* __restrict__ x, const float* __restrict__ W1,
    const void* __restrict__ edges, int n, int E, int nbT) {
    gdc_launch_dependents();
    if (blockIdx.x < nbT) {
        // ---- transform branch: independent of init_detect, no wait ----
        __shared__ float Ws[FIN * HID];  // 8 KB
        for (int i = threadIdx.x; i < FIN * HID; i += blockDim.x) Ws[i] = W1[i];
        __syncthreads();

        int node = blockIdx.x * blockDim.x + threadIdx.x;
        if (node >= n) return;

        {
            float4 z = make_float4(0.f, 0.f, 0.f, 0.f);
            float4* a = (float4*)(g_agg + (size_t)node * HID);
            a[0] = z; a[1] = z; a[2] = z; a[3] = z;
        }

        const float4* xr = (const float4*)(x + (size_t)node * FIN);
        unsigned long long acc[8];
#pragma unroll
        for (int j = 0; j < 8; j++) acc[j] = 0ULL;

#pragma unroll 8
        for (int k4 = 0; k4 < FIN / 4; k4++) {
            float4 xv = xr[k4];
#pragma unroll
            for (int sub = 0; sub < 4; sub++) {
                float xs = (sub == 0) ? xv.x : (sub == 1) ? xv.y : (sub == 2) ? xv.z : xv.w;
                unsigned long long xp = pack2(xs);
                const unsigned long long* wr =
                    (const unsigned long long*)(Ws + (k4 * 4 + sub) * HID);
#pragma unroll
                for (int j = 0; j < 8; j++) fma2(acc[j], xp, wr[j]);
            }
        }

        float hrow[16];
#pragma unroll
        for (int j = 0; j < 8; j++) {
            unsigned int lo, hi;
            asm("mov.b64 {%0, %1}, %2;" : "=r"(lo), "=r"(hi) : "l"(acc[j]));
            hrow[2 * j]     = __uint_as_float(lo);
            hrow[2 * j + 1] = __uint_as_float(hi);
        }
        float4* hout = (float4*)(g_h + (size_t)node * HID);
#pragma unroll
        for (int q = 0; q < 4; q++)
            hout[q] = make_float4(hrow[4 * q], hrow[4 * q + 1],
                                  hrow[4 * q + 2], hrow[4 * q + 3]);
    } else {
        // ---- degree branch: depends on init (g_is64, g_deg=1) ----
        gdc_wait();
        int is64 = g_is64;
        long long t = (long long)(blockIdx.x - nbT) * blockDim.x + threadIdx.x;
        long long base = t * DEG_EPT;
        if (base >= E) return;
        if (base + DEG_EPT <= E) {
            int dd[DEG_EPT];
            if (is64) {
                const longlong2* p =
                    (const longlong2*)((const long long*)edges + E + base);
                longlong2 a = p[0], b = p[1];
                dd[0] = (int)a.x; dd[1] = (int)a.y; dd[2] = (int)b.x; dd[3] = (int)b.y;
            } else {
                int4 a = *(const int4*)((const int*)edges + E + base);
                dd[0] = a.x; dd[1] = a.y; dd[2] = a.z; dd[3] = a.w;
            }
#pragma unroll
            for (int k = 0; k < DEG_EPT; k++)
                asm volatile("red.global.add.f32 [%0], %1;"
                             :: "l"(&g_deg[dd[k]]), "f"(1.0f) : "memory");
        } else {
            for (long long e = base; e < E; e++) {
                int d = edge_at(edges, (long long)E + e, is64);
                asm volatile("red.global.add.f32 [%0], %1;"
                             :: "l"(&g_deg[d]), "f"(1.0f) : "memory");
            }
        }
    }
}

// ---------------------------------------------------------------------------
// dinv = rsqrt(deg); h[i] *= dinv. Triggers dependents AFTER wait so that
// scatter's pre-wait prologue is guaranteed to see completed init+transform.
// ---------------------------------------------------------------------------
__global__ void __launch_bounds__(256) rsqrt_scale_kernel(int n) {
    gdc_wait();
    gdc_launch_dependents();
    int i = blockIdx.x * blockDim.x + threadIdx.x;
    if (i >= n) return;
    float dinv = rsqrtf(g_deg[i]);
    g_deg[i] = dinv;
    float4* h = (float4*)(g_h + (size_t)i * HID);
#pragma unroll
    for (int q = 0; q < 4; q++) {
        float4 v = h[q];
        v.x *= dinv; v.y *= dinv; v.z *= dinv; v.w *= dinv;
        h[q] = v;
    }
}

// ---------------------------------------------------------------------------
// edge scatter: agg[dst] += h_s[src]  [measured floor configuration]
// 4 threads/edge-quarter; each thread handles quarters t and t + half.
// iter-0 indices prefetched pre-wait (inputs + completed upstream only).
// ---------------------------------------------------------------------------
__global__ void __launch_bounds__(256) scatter_kernel(const void* __restrict__ edges,
                                                      int E, long long half) {
    gdc_launch_dependents();  // finalize pre-wait touches inputs only: safe
    int is64 = g_is64;
    long long totalq = 4LL * E;
    long long t = (long long)blockIdx.x * blockDim.x + threadIdx.x;
    int s0 = 0, d0 = 0;
    bool h0 = (t < totalq);
    long long e0 = t >> 2;
    int q0 = (int)(t & 3);
    if (h0) {
        s0 = edge_at(edges, e0, is64);
        d0 = edge_at(edges, (long long)E + e0, is64);
    }
    gdc_wait();
    if (h0) {
        float4 v = ((const float4*)(g_h + (size_t)s0 * HID))[q0];
        float* ad = g_agg + (size_t)d0 * HID + 4 * q0;
        asm volatile("red.global.add.v4.f32 [%0], {%1, %2, %3, %4};"
                     :: "l"(ad), "f"(v.x), "f"(v.y), "f"(v.z), "f"(v.w)
                     : "memory");
    }
    t += half;
    if (t < totalq) {
        long long e = t >> 2;
        int q = (int)(t & 3);
        int s = edge_at(edges, e, is64);
        int d = edge_at(edges, (long long)E + e, is64);
        float4 v = ((const float4*)(g_h + (size_t)s * HID))[q];
        float* ad = g_agg + (size_t)d * HID + 4 * q;
        asm volatile("red.global.add.v4.f32 [%0], {%1, %2, %3, %4};"
                     :: "l"(ad), "f"(v.x), "f"(v.y), "f"(v.z), "f"(v.w)
                     : "memory");
    }
}

// ---------------------------------------------------------------------------
// epilogue: a = relu(dinv*(agg + h_s) + b1), logits = a@Wp+bp, softmax
// (smem weight loads pre-wait)
// ---------------------------------------------------------------------------
__global__ void __launch_bounds__(256) finalize_kernel(
    const float* __restrict__ b1, const float* __restrict__ Wp,
    const float* __restrict__ bp, float* __restrict__ out, int n) {
    __shared__ float Wps[HID * CLS];
    __shared__ float bps[CLS];
    __shared__ float b1s[HID];
    for (int i = threadIdx.x; i < HID * CLS; i += blockDim.x) Wps[i] = Wp[i];
    if (threadIdx.x < CLS) bps[threadIdx.x] = bp[threadIdx.x];
    if (threadIdx.x < HID) b1s[threadIdx.x] = b1[threadIdx.x];
    gdc_wait();
    __syncthreads();

    int i = blockIdx.x * blockDim.x + threadIdx.x;
    if (i >= n) return;

    float dinv = g_deg[i];

    float a[HID];
    const float4* ag = (const float4*)(g_agg + (size_t)i * HID);
    const float4* hv = (const float4*)(g_h + (size_t)i * HID);
#pragma unroll
    for (int q = 0; q < 4; q++) {
        float4 av = ag[q];
        float4 hh = hv[q];
        a[4 * q + 0] = fmaxf(fmaf(av.x + hh.x, dinv, b1s[4 * q + 0]), 0.0f);
        a[4 * q + 1] = fmaxf(fmaf(av.y + hh.y, dinv, b1s[4 * q + 1]), 0.0f);
        a[4 * q + 2] = fmaxf(fmaf(av.z + hh.z, dinv, b1s[4 * q + 2]), 0.0f);
        a[4 * q + 3] = fmaxf(fmaf(av.w + hh.w, dinv, b1s[4 * q + 3]), 0.0f);
    }

    float lg[CLS];
#pragma unroll
    for (int c = 0; c < CLS; c++) lg[c] = bps[c];
#pragma unroll
    for (int j = 0; j < HID; j++) {
        float aj = a[j];
#pragma unroll
        for (int c = 0; c < CLS; c++) lg[c] = fmaf(aj, Wps[j * CLS + c], lg[c]);
    }

    float m = lg[0];
#pragma unroll
    for (int c = 1; c < CLS; c++) m = fmaxf(m, lg[c]);
    float ssum = 0.0f;
#pragma unroll
    for (int c = 0; c < CLS; c++) { lg[c] = __expf(lg[c] - m); ssum += lg[c]; }
    float inv = 1.0f / ssum;
#pragma unroll
    for (int c = 0; c < CLS; c++) lg[c] *= inv;

    float4* o = (float4*)(out + (size_t)i * CLS);
#pragma unroll
    for (int q = 0; q < 4; q++)
        o[q] = make_float4(lg[4 * q], lg[4 * q + 1], lg[4 * q + 2], lg[4 * q + 3]);
}

// ---------------------------------------------------------------------------
// launch (5 kernels, PDL edges between consecutive ones)
// ---------------------------------------------------------------------------
template <typename... ExpT, typename... ActT>
static void launch_k(void (*k)(ExpT...), int grid, bool pdl, ActT... args) {
    cudaLaunchConfig_t cfg = {};
    cfg.gridDim = dim3((unsigned)grid, 1, 1);
    cfg.blockDim = dim3(256, 1, 1);
    cfg.dynamicSmemBytes = 0;
    cfg.stream = 0;  // legacy default stream (same as <<<>>>)
    cudaLaunchAttribute attr[1];
    if (pdl) {
        attr[0].id = cudaLaunchAttributeProgrammaticStreamSerialization;
        attr[0].val.programmaticStreamSerializationAllowed = 1;
        cfg.attrs = attr;
        cfg.numAttrs = 1;
    }
    cudaLaunchKernelEx(&cfg, k, args...);
}

extern "C" void kernel_launch(void* const* d_in, const int* in_sizes, int n_in,
                              void* d_out, int out_size) {
    const float* x  = (const float*)d_in[0];
    const float* W1 = (const float*)d_in[1];
    const float* b1 = (const float*)d_in[2];
    const float* Wp = (const float*)d_in[3];
    const float* bp = (const float*)d_in[4];
    const void*  edges = d_in[5];

    int n = in_sizes[0] / FIN;       // 100000
    int E = in_sizes[5] / 2;         // 3200000

    int nb  = (n + 255) / 256;
    int nbT = nb;
    int degBlocks = (E + 256 * DEG_EPT - 1) / (256 * DEG_EPT);

    long long totalq = 4LL * E;
    long long half = (totalq + 1) / 2;
    int sb = (int)((half + 255) / 256);

    launch_k(init_detect_kernel, nb, false, n, (const int*)edges, in_sizes[5]);
    launch_k(transform_deg_kernel, nbT + degBlocks, true, x, W1, edges, n, E, nbT);
    launch_k(rsqrt_scale_kernel, nb, true, n);
    launch_k(scatter_kernel, sb, true, edges, E, half);
    launch_k(finalize_kernel, nb, true, b1, Wp, bp, (float*)d_out, n);
}